// round 12
// baseline (speedup 1.0000x reference)
#include <cuda_runtime.h>
#include <cstdint>

#define BATCH  8
#define HWDIM  64
#define CCH    256
#define RED    64
#define EE     144     // K*K*G = 9*16
#define NTHR   512

// ---- smem layout (32-bit word offsets) ----
#define XH_STRIDE  260
#define OFF_XH     0                    // 100*260 = 26000 (fp32)
#define OFF_W1H    26000                // 64*132 = 8448 (bf16x2, [n][step-interleaved k/2])
#define W1P_STRIDE 132
#define OFF_W1L    34448                // 8448 ; planes end 42896
#define OFF_WGT    26000                // overlay W1 planes after stage1: 64*145 = 9280
#define WGT_STRIDE 145
#define OFF_W2H    42896                // 144*36 = 5184
#define W2P_STRIDE 36
#define OFF_W2L    48080                // 5184 ; end 53264
#define OFF_MIDH   53264                // 64*36 = 2304 (bf16x2 planes, interleaved)
#define MID_STRIDE 36
#define OFF_MIDL   55568                // 2304 ; end 57872
#define OFF_B1     57872                // 64
#define OFF_B2     57936                // 144
#define SMEM_WORDS 58080
#define SMEM_BYTES (SMEM_WORDS * 4)     // 232320 B <= 232448 limit, 1 CTA/SM

// m16n8k16 bf16 mma: D += A(16x16 row) * B(16x8 col)
__device__ __forceinline__ void mma_bf16(float d[4],
    uint32_t a0, uint32_t a1, uint32_t a2, uint32_t a3,
    uint32_t b0, uint32_t b1)
{
    asm volatile(
        "mma.sync.aligned.m16n8k16.row.col.f32.bf16.bf16.f32 "
        "{%0,%1,%2,%3}, {%4,%5,%6,%7}, {%8,%9}, {%0,%1,%2,%3};"
        : "+f"(d[0]), "+f"(d[1]), "+f"(d[2]), "+f"(d[3])
        : "r"(a0), "r"(a1), "r"(a2), "r"(a3), "r"(b0), "r"(b1));
}

// pack (v0,v1) -> bf16x2 hi and bf16x2 residual lo
__device__ __forceinline__ void bf16_split_pair(float v0, float v1,
                                                uint32_t& hi, uint32_t& lo)
{
    uint32_t h;
    asm("cvt.rn.bf16x2.f32 %0, %1, %2;" : "=r"(h) : "f"(v1), "f"(v0));
    float h0 = __uint_as_float(h << 16);
    float h1 = __uint_as_float(h & 0xFFFF0000u);
    float l0 = v0 - h0;
    float l1 = v1 - h1;
    asm("cvt.rn.bf16x2.f32 %0, %1, %2;" : "=r"(lo) : "f"(l1), "f"(l0));
    hi = h;
}

__device__ __forceinline__ void cp_async16(uint32_t daddr, const void* src, int sz)
{
    asm volatile("cp.async.cg.shared.global [%0], [%1], 16, %2;"
                 :: "r"(daddr), "l"(src), "r"(sz));
}

__global__ void __launch_bounds__(NTHR, 1)
invo_mma_kernel(const float* __restrict__ x,
                const float* __restrict__ W1,
                const float* __restrict__ b1,
                const float* __restrict__ W2,
                const float* __restrict__ b2,
                float* __restrict__ out)
{
    extern __shared__ float s[];
    uint32_t* su = (uint32_t*)s;
    const int t  = threadIdx.x;
    const int bb = blockIdx.z;
    const int h0 = blockIdx.y * 8;
    const int w0 = blockIdx.x * 8;

    uint32_t s_base;
    asm("{ .reg .u64 tt; cvta.to.shared.u64 tt, %1; cvt.u32.u64 %0, tt; }"
        : "=r"(s_base) : "l"(s));

    // ---- Phase 0a: halo 10x10x256 fp32 via cp.async (zero-fill OOB) ----
    #pragma unroll
    for (int it = 0; it < 13; it++) {
        int i4 = t + it * NTHR;            // 0..6399 float4s
        if (i4 < 6400) {
            int c4 = i4 & 63;
            int sp = i4 >> 6;              // 0..99
            int r  = sp / 10;
            int cl = sp - r * 10;
            int gh = h0 - 1 + r;
            int gw = w0 - 1 + cl;
            bool ok = ((unsigned)gh < HWDIM) && ((unsigned)gw < HWDIM);
            const float* gp = ok
                ? x + ((size_t)((bb * HWDIM + gh) * HWDIM + gw) * CCH) + c4 * 4
                : x;
            cp_async16(s_base + (OFF_XH + sp * XH_STRIDE + c4 * 4) * 4, gp, ok ? 16 : 0);
        }
    }
    asm volatile("cp.async.commit_group;" ::: "memory");

    // ---- Phase 0b: W1 -> interleaved bf16 planes [n][s*8 + 2*(p&3) + (p>>2)] ----
    #pragma unroll
    for (int it = 0; it < 2; it++) {
        int u = t + it * NTHR;             // 1024 units: (n, k16-step)
        int n  = u & 63;
        int st = u >> 6;                   // 0..15
        float v[16];
        #pragma unroll
        for (int j = 0; j < 16; j++) v[j] = W1[(st * 16 + j) * RED + n];
        uint32_t h[8], l[8];
        #pragma unroll
        for (int p = 0; p < 8; p++) bf16_split_pair(v[2*p], v[2*p+1], h[p], l[p]);
        int base = n * W1P_STRIDE + st * 8;
        *(uint4*)(su + OFF_W1H + base)     = make_uint4(h[0], h[4], h[1], h[5]);
        *(uint4*)(su + OFF_W1H + base + 4) = make_uint4(h[2], h[6], h[3], h[7]);
        *(uint4*)(su + OFF_W1L + base)     = make_uint4(l[0], l[4], l[1], l[5]);
        *(uint4*)(su + OFF_W1L + base + 4) = make_uint4(l[2], l[6], l[3], l[7]);
    }
    // ---- Phase 0c: W2 -> interleaved bf16 planes [e][s*8 + ...]  (576 units!) ----
    #pragma unroll
    for (int it = 0; it < 2; it++) {
        int u = t + it * NTHR;             // 576 units: (e, k16-step)
        if (u < 576) {
            int st = u / 144;              // 0..3
            int e  = u - st * 144;
            float v[16];
            #pragma unroll
            for (int j = 0; j < 16; j++) v[j] = W2[(st * 16 + j) * EE + e];
            uint32_t h[8], l[8];
            #pragma unroll
            for (int p = 0; p < 8; p++) bf16_split_pair(v[2*p], v[2*p+1], h[p], l[p]);
            int base = e * W2P_STRIDE + st * 8;
            *(uint4*)(su + OFF_W2H + base)     = make_uint4(h[0], h[4], h[1], h[5]);
            *(uint4*)(su + OFF_W2H + base + 4) = make_uint4(h[2], h[6], h[3], h[7]);
            *(uint4*)(su + OFF_W2L + base)     = make_uint4(l[0], l[4], l[1], l[5]);
            *(uint4*)(su + OFF_W2L + base + 4) = make_uint4(l[2], l[6], l[3], l[7]);
        }
    }
    if (t < RED) s[OFF_B1 + t] = b1[t];
    else if (t >= 128 && t < 128 + EE) s[OFF_B2 + (t - 128)] = b2[t - 128];
    asm volatile("cp.async.wait_group 0;" ::: "memory");
    __syncthreads();

    const int warp = t >> 5, lane = t & 31;
    const int gid = lane >> 2, t4 = lane & 3;

    // ---- Stage 1: mid[64px][64] = x @ W1 + b1   (3-term bf16 k16) ----
    // 16 warps: (warp>>2) = m-tile (16 rows), (warp&3) = n-quarter (2 ntiles of 8)
    {
        const int m0 = (warp >> 2) * 16;
        const int nb = (warp & 3) * 16;
        const int px0 = m0 + gid, px1 = px0 + 8;
        const int sp0 = OFF_XH + (((px0 >> 3) + 1) * 10 + (px0 & 7) + 1) * XH_STRIDE;
        const int sp1 = OFF_XH + (((px1 >> 3) + 1) * 10 + (px1 & 7) + 1) * XH_STRIDE;
        float Dm[2][4], Dc[2][4];
        #pragma unroll
        for (int nt = 0; nt < 2; nt++)
            #pragma unroll
            for (int i = 0; i < 4; i++) { Dm[nt][i] = 0.f; Dc[nt][i] = 0.f; }

        #pragma unroll 4
        for (int k0 = 0; k0 < CCH; k0 += 16) {
            float2 p0 = *(const float2*)(s + sp0 + k0 + 2 * t4);
            float2 p1 = *(const float2*)(s + sp1 + k0 + 2 * t4);
            float2 p2 = *(const float2*)(s + sp0 + k0 + 8 + 2 * t4);
            float2 p3 = *(const float2*)(s + sp1 + k0 + 8 + 2 * t4);
            uint32_t ah[4], al[4];
            bf16_split_pair(p0.x, p0.y, ah[0], al[0]);
            bf16_split_pair(p1.x, p1.y, ah[1], al[1]);
            bf16_split_pair(p2.x, p2.y, ah[2], al[2]);
            bf16_split_pair(p3.x, p3.y, ah[3], al[3]);
            const int sw = (k0 >> 1) + 2 * t4;       // s*8 + 2*t4
            #pragma unroll
            for (int nt = 0; nt < 2; nt++) {
                int n = nb + nt * 8 + gid;
                uint2 bh = *(const uint2*)(su + OFF_W1H + n * W1P_STRIDE + sw);
                uint2 bl = *(const uint2*)(su + OFF_W1L + n * W1P_STRIDE + sw);
                mma_bf16(Dm[nt], ah[0], ah[1], ah[2], ah[3], bh.x, bh.y);
                mma_bf16(Dc[nt], al[0], al[1], al[2], al[3], bh.x, bh.y);
                mma_bf16(Dc[nt], ah[0], ah[1], ah[2], ah[3], bl.x, bl.y);
            }
        }
        // epilogue: pack mid pairs into interleaved bf16 planes
        #pragma unroll
        for (int nt = 0; nt < 2; nt++) {
            int n0 = nb + nt * 8 + 2 * t4;
            float bia0 = s[OFF_B1 + n0], bia1 = s[OFF_B1 + n0 + 1];
            int word = (nb >> 1) + 2 * t4 + nt;      // s*8 + 2*t4 + nt, s = nb/16
            uint32_t h, l;
            bf16_split_pair(Dm[nt][0] + Dc[nt][0] + bia0,
                            Dm[nt][1] + Dc[nt][1] + bia1, h, l);
            su[OFF_MIDH + (m0 + gid) * MID_STRIDE + word] = h;
            su[OFF_MIDL + (m0 + gid) * MID_STRIDE + word] = l;
            bf16_split_pair(Dm[nt][2] + Dc[nt][2] + bia0,
                            Dm[nt][3] + Dc[nt][3] + bia1, h, l);
            su[OFF_MIDH + (m0 + gid + 8) * MID_STRIDE + word] = h;
            su[OFF_MIDL + (m0 + gid + 8) * MID_STRIDE + word] = l;
        }
    }
    __syncthreads();

    // ---- Stage 2: wgt[64px][144] = mid @ W2 + b2  (pure-LDS feed; wgt over W1 planes) ----
    {
        const int m0 = (warp >> 2) * 16;
        const int nset = warp & 3;
        float Dm[5][4], Dc[5][4];
        #pragma unroll
        for (int j = 0; j < 5; j++)
            #pragma unroll
            for (int i = 0; i < 4; i++) { Dm[j][i] = 0.f; Dc[j][i] = 0.f; }

        #pragma unroll
        for (int k0 = 0; k0 < RED; k0 += 16) {
            const int sw = (k0 >> 1) + 2 * t4;
            uint2 ahp0 = *(const uint2*)(su + OFF_MIDH + (m0 + gid)     * MID_STRIDE + sw);
            uint2 ahp1 = *(const uint2*)(su + OFF_MIDH + (m0 + gid + 8) * MID_STRIDE + sw);
            uint2 alp0 = *(const uint2*)(su + OFF_MIDL + (m0 + gid)     * MID_STRIDE + sw);
            uint2 alp1 = *(const uint2*)(su + OFF_MIDL + (m0 + gid + 8) * MID_STRIDE + sw);
            #pragma unroll
            for (int jj = 0; jj < 5; jj++) {
                int j = nset + jj * 4;
                if (j < 18) {
                    int e = j * 8 + gid;
                    uint2 bh = *(const uint2*)(su + OFF_W2H + e * W2P_STRIDE + sw);
                    uint2 bl = *(const uint2*)(su + OFF_W2L + e * W2P_STRIDE + sw);
                    mma_bf16(Dm[jj], ahp0.x, ahp1.x, ahp0.y, ahp1.y, bh.x, bh.y);
                    mma_bf16(Dc[jj], alp0.x, alp1.x, alp0.y, alp1.y, bh.x, bh.y);
                    mma_bf16(Dc[jj], ahp0.x, ahp1.x, ahp0.y, ahp1.y, bl.x, bl.y);
                }
            }
        }
        #pragma unroll
        for (int jj = 0; jj < 5; jj++) {
            int j = nset + jj * 4;
            if (j < 18) {
                int e0 = j * 8 + 2 * t4;
                float bb0 = s[OFF_B2 + e0], bb1 = s[OFF_B2 + e0 + 1];
                s[OFF_WGT + (m0 + gid)     * WGT_STRIDE + e0]     = Dm[jj][0] + Dc[jj][0] + bb0;
                s[OFF_WGT + (m0 + gid)     * WGT_STRIDE + e0 + 1] = Dm[jj][1] + Dc[jj][1] + bb1;
                s[OFF_WGT + (m0 + gid + 8) * WGT_STRIDE + e0]     = Dm[jj][2] + Dc[jj][2] + bb0;
                s[OFF_WGT + (m0 + gid + 8) * WGT_STRIDE + e0 + 1] = Dm[jj][3] + Dc[jj][3] + bb1;
            }
        }
    }
    __syncthreads();

    // ---- Stage 3: involution, float4 halo reads, direct STG ----
    {
        const int half = warp & 1, gset = warp >> 1;
        const int pr = half * 4 + (lane >> 3), pc = lane & 7;
        const int wbase = OFF_WGT + (pr * 8 + pc) * WGT_STRIDE;
        const int xb = OFF_XH + (pr * 10 + pc) * XH_STRIDE;   // tap (di=0,dj=0)
        float* op = out + ((size_t)((bb * HWDIM + h0 + pr) * HWDIM + (w0 + pc))) * CCH;
        #pragma unroll
        for (int gi = 0; gi < 2; gi++) {
            int g = gset * 2 + gi;
            float wv[9];
            #pragma unroll
            for (int k = 0; k < 9; k++) wv[k] = s[wbase + g * 9 + k];
            int F0g = g * 36;
            int ko0 = F0g >> 6;
            int cs0 = F0g & 63;
            int tc  = 64 - cs0;                    // f4-idx count before boundary
            int di0 = (ko0 * 11) >> 5, dj0 = ko0 - 3 * di0;
            int ko1 = ko0 + 1;
            int di1 = (ko1 * 11) >> 5, dj1 = ko1 - 3 * di1;
            int A0 = xb + (di0 * 10 + dj0) * XH_STRIDE + cs0 * 4;   // + idx*4
            int A1 = xb + (di1 * 10 + dj1) * XH_STRIDE - tc * 4;    // + idx*4 (idx>=tc)
            #pragma unroll
            for (int c = 0; c < 4; c++) {
                float acc[4] = {0.f, 0.f, 0.f, 0.f};
                #pragma unroll
                for (int j = 0; j < 9; j++) {
                    const int idx = c * 9 + j;
                    int addr = ((idx < tc) ? A0 : A1) + idx * 4;
                    const float4 xv = *(const float4*)(s + addr);
                    const int fl = idx * 4;        // float index within group's 144
                    acc[(fl + 0) / 9 - c * 4] += wv[(fl + 0) % 9] * xv.x;
                    acc[(fl + 1) / 9 - c * 4] += wv[(fl + 1) % 9] * xv.y;
                    acc[(fl + 2) / 9 - c * 4] += wv[(fl + 2) % 9] * xv.z;
                    acc[(fl + 3) / 9 - c * 4] += wv[(fl + 3) % 9] * xv.w;
                }
                *(float4*)(op + g * 16 + c * 4) =
                    make_float4(acc[0], acc[1], acc[2], acc[3]);
            }
        }
    }
}

extern "C" void kernel_launch(void* const* d_in, const int* in_sizes, int n_in,
                              void* d_out, int out_size)
{
    (void)in_sizes; (void)n_in; (void)out_size;
    const float* x  = (const float*)d_in[0];
    const float* W1 = (const float*)d_in[1];
    const float* b1 = (const float*)d_in[2];
    const float* W2 = (const float*)d_in[3];
    const float* b2 = (const float*)d_in[4];
    float* out = (float*)d_out;

    cudaFuncSetAttribute(invo_mma_kernel,
                         cudaFuncAttributeMaxDynamicSharedMemorySize, SMEM_BYTES);
    dim3 grid(HWDIM / 8, HWDIM / 8, BATCH);   // (8, 8, 8) = 512 CTAs
    invo_mma_kernel<<<grid, NTHR, SMEM_BYTES>>>(x, W1, b1, W2, b2, out);
}